// round 5
// baseline (speedup 1.0000x reference)
#include <cuda_runtime.h>
#include <cuda_bf16.h>

#define C 4096
#define MV_THREADS 256

// Scratch (allocation-free rule: __device__ globals)
__device__ float g_kvr_p[2][3 * C];   // K-split partial sums: [kc][mat*C+row]

// ---------------------------------------------------------------------------
// K_A: fused mix + three matvecs (kw@xk, vw@xv, rw@xr), K split in 2.
// grid = (512, 2, 3). Each block: recompute its mix chunk into smem, then
// 8 warps x 1 row x 2048-col partial dot. Also: side-job writes new_state=x
// and zeroes out[0:C]; every thread issues one L2 prefetch of an ow line.
// ---------------------------------------------------------------------------
__global__ __launch_bounds__(MV_THREADS)
void matvec3_fused_kernel(const float* __restrict__ kw,
                          const float* __restrict__ vw,
                          const float* __restrict__ rw,
                          const float* __restrict__ ow,
                          const float* __restrict__ x,
                          const float* __restrict__ state,
                          const float* __restrict__ tmk,
                          const float* __restrict__ tmv,
                          const float* __restrict__ tmr,
                          float* __restrict__ d_out) {
    __shared__ __align__(16) float s_x[2048];   // mixed x chunk (8 KB)

    int tid  = threadIdx.x;
    int kc   = blockIdx.y;
    int mat  = blockIdx.z;
    int col0 = kc * 2048;

    const float* W  = (mat == 0) ? kw  : (mat == 1) ? vw  : rw;
    const float* tm = (mat == 0) ? tmk : (mat == 1) ? tmv : tmr;

    // ---- mix preamble: s_x[i] = state + (x - state) * tm  over col chunk
    {
        const float4* x4 = reinterpret_cast<const float4*>(x + col0);
        const float4* s4 = reinterpret_cast<const float4*>(state + col0);
        const float4* m4 = reinterpret_cast<const float4*>(tm + col0);
        float4* sx4 = reinterpret_cast<float4*>(s_x);
#pragma unroll
        for (int u = 0; u < 2; u++) {
            int i4 = tid + u * MV_THREADS;
            float4 xv = __ldg(&x4[i4]);
            float4 sv = __ldg(&s4[i4]);
            float4 mv = __ldg(&m4[i4]);
            float4 r;
            r.x = fmaf(xv.x - sv.x, mv.x, sv.x);
            r.y = fmaf(xv.y - sv.y, mv.y, sv.y);
            r.z = fmaf(xv.z - sv.z, mv.z, sv.z);
            r.w = fmaf(xv.w - sv.w, mv.w, sv.w);
            sx4[i4] = r;
        }
    }

    // ---- side job: new_state = x, out accumulator = 0 (16 blocks cover C)
    if (mat == 0 && kc == 0 && blockIdx.x < 16) {
        int j = blockIdx.x * MV_THREADS + tid;
        d_out[j]     = 0.0f;
        d_out[C + j] = x[j];
    }

    // ---- prefetch one 128B line of ow into L2 (fills DRAM slack of phase A)
    {
        unsigned gtid = ((blockIdx.z * 2u + blockIdx.y) * 512u + blockIdx.x) * MV_THREADS + tid;
        if (gtid < (unsigned)(C * C / 32)) {   // 524288 lines of 128 B
            const char* p = reinterpret_cast<const char*>(ow) + (size_t)gtid * 128;
            asm volatile("prefetch.global.L2 [%0];" :: "l"(p));
        }
    }
    __syncthreads();

    // ---- partial row dot: warp w -> row, 16 float4 per lane
    int warp = tid >> 5;
    int lane = tid & 31;
    int row  = blockIdx.x * 8 + warp;

    const float4* Wr  = reinterpret_cast<const float4*>(W + (size_t)row * C + col0);
    const float4* sx4 = reinterpret_cast<const float4*>(s_x);

    float4 a0 = make_float4(0.f, 0.f, 0.f, 0.f);
    float4 a1 = make_float4(0.f, 0.f, 0.f, 0.f);
#pragma unroll
    for (int j = 0; j < 16; j += 2) {
        float4 w0 = __ldcs(&Wr[lane + (j + 0) * 32]);
        float4 w1 = __ldcs(&Wr[lane + (j + 1) * 32]);
        float4 x0 = sx4[lane + (j + 0) * 32];
        float4 x1 = sx4[lane + (j + 1) * 32];
        a0.x = fmaf(w0.x, x0.x, a0.x); a0.y = fmaf(w0.y, x0.y, a0.y);
        a0.z = fmaf(w0.z, x0.z, a0.z); a0.w = fmaf(w0.w, x0.w, a0.w);
        a1.x = fmaf(w1.x, x1.x, a1.x); a1.y = fmaf(w1.y, x1.y, a1.y);
        a1.z = fmaf(w1.z, x1.z, a1.z); a1.w = fmaf(w1.w, x1.w, a1.w);
    }
    float s = ((a0.x + a0.y) + (a0.z + a0.w))
            + ((a1.x + a1.y) + (a1.z + a1.w));
#pragma unroll
    for (int o = 16; o > 0; o >>= 1)
        s += __shfl_xor_sync(0xFFFFFFFFu, s, o);
    if (lane == 0) g_kvr_p[kc][mat * C + row] = s;
}

// ---------------------------------------------------------------------------
// K_B: fused wkv + ow matvec, K split in 4. grid = (512, 4).
// Preamble: each block recomputes wkv for its 1024-column chunk (reads the
// two kvr partials + state vectors — L2 hits after first touch), writes
// new_state_a/b/p (only blockIdx.x==0), y -> smem. Then 8 warps x 1 row
// partial dot over ow columns (L2-resident via K_A prefetch), atomicAdd out.
// ---------------------------------------------------------------------------
__global__ __launch_bounds__(MV_THREADS)
void ow_fused_kernel(const float* __restrict__ ow,
                     const float* __restrict__ state_a,
                     const float* __restrict__ state_b,
                     const float* __restrict__ state_p,
                     const float* __restrict__ time_first,
                     const float* __restrict__ time_decay,
                     float* __restrict__ d_out) {
    __shared__ __align__(16) float s_y[1024];   // r*wkv chunk (4 KB)

    int tid  = threadIdx.x;
    int kc   = blockIdx.y;
    int col0 = kc * 1024;

    // ---- wkv preamble: 4 elements per thread
    {
        int e = col0 + tid * 4;
        const float* p0 = g_kvr_p[0];
        const float* p1 = g_kvr_p[1];
#pragma unroll
        for (int c = 0; c < 4; c++) {
            int i = e + c;
            float kk = p0[i]         + p1[i];
            float vv = p0[C + i]     + p1[C + i];
            float rr = p0[2 * C + i] + p1[2 * C + i];
            float aa = __ldg(&state_a[i]);
            float bb = __ldg(&state_b[i]);
            float pp = __ldg(&state_p[i]);
            float tf = __ldg(&time_first[i]);
            float td = __ldg(&time_decay[i]);

            float r = 1.0f / (1.0f + expf(-rr));

            float ww = tf + kk;
            float p  = fmaxf(pp, ww);
            float e1 = expf(pp - p);
            float e2 = expf(ww - p);
            float a  = e1 * aa + e2 * vv;
            float b  = e1 * bb + e2;

            if (blockIdx.x == 0) {
                float ww2 = pp + td;
                float p2  = fmaxf(ww2, kk);
                float f1  = expf(ww2 - p2);
                float f2  = expf(kk - p2);
                d_out[2 * C + i] = f1 * aa + f2 * vv;  // new_state_a
                d_out[3 * C + i] = f1 * bb + f2;       // new_state_b
                d_out[4 * C + i] = p2;                 // new_state_p
            }
            s_y[tid * 4 + c] = r * (a / b);
        }
    }
    __syncthreads();

    // ---- partial row dot over ow columns col0..col0+1023 (8 float4/lane)
    int warp = tid >> 5;
    int lane = tid & 31;
    int row  = blockIdx.x * 8 + warp;

    const float4* Or  = reinterpret_cast<const float4*>(ow + (size_t)row * C + col0);
    const float4* sy4 = reinterpret_cast<const float4*>(s_y);

    float4 a0 = make_float4(0.f, 0.f, 0.f, 0.f);
    float4 a1 = make_float4(0.f, 0.f, 0.f, 0.f);
#pragma unroll
    for (int j = 0; j < 8; j += 2) {
        float4 w0 = __ldg(&Or[lane + (j + 0) * 32]);
        float4 w1 = __ldg(&Or[lane + (j + 1) * 32]);
        float4 x0 = sy4[lane + (j + 0) * 32];
        float4 x1 = sy4[lane + (j + 1) * 32];
        a0.x = fmaf(w0.x, x0.x, a0.x); a0.y = fmaf(w0.y, x0.y, a0.y);
        a0.z = fmaf(w0.z, x0.z, a0.z); a0.w = fmaf(w0.w, x0.w, a0.w);
        a1.x = fmaf(w1.x, x1.x, a1.x); a1.y = fmaf(w1.y, x1.y, a1.y);
        a1.z = fmaf(w1.z, x1.z, a1.z); a1.w = fmaf(w1.w, x1.w, a1.w);
    }
    float s = ((a0.x + a0.y) + (a0.z + a0.w))
            + ((a1.x + a1.y) + (a1.z + a1.w));
#pragma unroll
    for (int o = 16; o > 0; o >>= 1)
        s += __shfl_xor_sync(0xFFFFFFFFu, s, o);
    if (lane == 0) atomicAdd(&d_out[row], s);
}

// ---------------------------------------------------------------------------
// Launch. Input order (metadata): x, state, state_a, state_b, state_p,
// time_mix_k, time_mix_v, time_mix_r, time_first, time_decay, kw, vw, rw, ow.
// Output layout: [out | new_state | new_state_a | new_state_b | new_state_p]
// ---------------------------------------------------------------------------
extern "C" void kernel_launch(void* const* d_in, const int* in_sizes, int n_in,
                              void* d_out, int out_size) {
    const float* x   = (const float*)d_in[0];
    const float* st  = (const float*)d_in[1];
    const float* sa  = (const float*)d_in[2];
    const float* sb  = (const float*)d_in[3];
    const float* sp  = (const float*)d_in[4];
    const float* tmk = (const float*)d_in[5];
    const float* tmv = (const float*)d_in[6];
    const float* tmr = (const float*)d_in[7];
    const float* tf  = (const float*)d_in[8];
    const float* td  = (const float*)d_in[9];
    const float* kw  = (const float*)d_in[10];
    const float* vw  = (const float*)d_in[11];
    const float* rw  = (const float*)d_in[12];
    const float* ow  = (const float*)d_in[13];
    float* out = (float*)d_out;

    dim3 gA(512, 2, 3);
    matvec3_fused_kernel<<<gA, MV_THREADS>>>(kw, vw, rw, ow, x, st,
                                             tmk, tmv, tmr, out);

    dim3 gB(512, 4);
    ow_fused_kernel<<<gB, MV_THREADS>>>(ow, sa, sb, sp, tf, td, out);
}

// round 6
// speedup vs baseline: 1.0754x; 1.0754x over previous
#include <cuda_runtime.h>
#include <cuda_bf16.h>

#define C 4096
#define MV_THREADS 256
#define KSPLIT_A 4            // matvec3 K-chunks of 1024
#define KSPLIT_OW 8           // ow K-chunks of 512

// Scratch (allocation-free rule: __device__ globals)
__device__ float g_kvr_p[KSPLIT_A][3 * C];  // per-chunk partials (plain stores)
__device__ float g_rwkv[C];                 // r * wkv

// ---------------------------------------------------------------------------
// K_A: fused mix + three matvecs, grid (512, 4, 3) = 6144 blocks.
// Block (bx, kc, mat): mix its 1024-col chunk into smem (redundant across bx
// but L1/L2-cached), then 8 warps x 1 row x 1024-col partial dot -> plain
// store into g_kvr_p[kc]. Side job: new_state = x.
// ---------------------------------------------------------------------------
__global__ __launch_bounds__(MV_THREADS)
void matvec3_fused_kernel(const float* __restrict__ kw,
                          const float* __restrict__ vw,
                          const float* __restrict__ rw,
                          const float* __restrict__ x,
                          const float* __restrict__ state,
                          const float* __restrict__ tmk,
                          const float* __restrict__ tmv,
                          const float* __restrict__ tmr,
                          float* __restrict__ d_out) {
    __shared__ __align__(16) float s_x[1024];   // mixed x chunk (4 KB)

    int tid  = threadIdx.x;
    int kc   = blockIdx.y;
    int mat  = blockIdx.z;
    int col0 = kc * 1024;

    const float* W  = (mat == 0) ? kw  : (mat == 1) ? vw  : rw;
    const float* tm = (mat == 0) ? tmk : (mat == 1) ? tmv : tmr;

    // ---- mix preamble: s_x = state + (x - state) * tm over this chunk
    {
        const float4* x4 = reinterpret_cast<const float4*>(x + col0);
        const float4* s4 = reinterpret_cast<const float4*>(state + col0);
        const float4* m4 = reinterpret_cast<const float4*>(tm + col0);
        float4 xv = __ldg(&x4[tid]);
        float4 sv = __ldg(&s4[tid]);
        float4 mv = __ldg(&m4[tid]);
        float4 r;
        r.x = fmaf(xv.x - sv.x, mv.x, sv.x);
        r.y = fmaf(xv.y - sv.y, mv.y, sv.y);
        r.z = fmaf(xv.z - sv.z, mv.z, sv.z);
        r.w = fmaf(xv.w - sv.w, mv.w, sv.w);
        reinterpret_cast<float4*>(s_x)[tid] = r;
    }

    // ---- side job: new_state = x (16 blocks cover C)
    if (mat == 0 && kc == 0 && blockIdx.x < 16) {
        int j = blockIdx.x * MV_THREADS + tid;
        d_out[C + j] = __ldg(&x[j]);
    }
    __syncthreads();

    // ---- partial row dot: warp -> row, 8 float4 per lane over 1024 cols
    int warp = tid >> 5;
    int lane = tid & 31;
    int row  = blockIdx.x * 8 + warp;

    const float4* Wr  = reinterpret_cast<const float4*>(W + (size_t)row * C + col0);
    const float4* sx4 = reinterpret_cast<const float4*>(s_x);

    float4 a0 = make_float4(0.f, 0.f, 0.f, 0.f);
    float4 a1 = make_float4(0.f, 0.f, 0.f, 0.f);
#pragma unroll
    for (int j = 0; j < 8; j += 2) {
        float4 w0 = __ldcs(&Wr[lane + (j + 0) * 32]);
        float4 w1 = __ldcs(&Wr[lane + (j + 1) * 32]);
        float4 x0 = sx4[lane + (j + 0) * 32];
        float4 x1 = sx4[lane + (j + 1) * 32];
        a0.x = fmaf(w0.x, x0.x, a0.x); a0.y = fmaf(w0.y, x0.y, a0.y);
        a0.z = fmaf(w0.z, x0.z, a0.z); a0.w = fmaf(w0.w, x0.w, a0.w);
        a1.x = fmaf(w1.x, x1.x, a1.x); a1.y = fmaf(w1.y, x1.y, a1.y);
        a1.z = fmaf(w1.z, x1.z, a1.z); a1.w = fmaf(w1.w, x1.w, a1.w);
    }
    float s = ((a0.x + a0.y) + (a0.z + a0.w))
            + ((a1.x + a1.y) + (a1.z + a1.w));
#pragma unroll
    for (int o = 16; o > 0; o >>= 1)
        s += __shfl_xor_sync(0xFFFFFFFFu, s, o);
    if (lane == 0) g_kvr_p[kc][mat * C + row] = s;
}

// ---------------------------------------------------------------------------
// K_B: wkv elementwise. Sums the 4 K-chunk partials, writes new_state_a/b/p,
// g_rwkv, and zeroes out[0:C] (atomic target for K_C).
// ---------------------------------------------------------------------------
__global__ void wkv_kernel(const float* __restrict__ state_a,
                           const float* __restrict__ state_b,
                           const float* __restrict__ state_p,
                           const float* __restrict__ time_first,
                           const float* __restrict__ time_decay,
                           float* __restrict__ d_out) {
    int i = blockIdx.x * blockDim.x + threadIdx.x;
    if (i >= C) return;

    float kk = 0.f, vv = 0.f, rr = 0.f;
#pragma unroll
    for (int kc = 0; kc < KSPLIT_A; kc++) {
        kk += g_kvr_p[kc][i];
        vv += g_kvr_p[kc][C + i];
        rr += g_kvr_p[kc][2 * C + i];
    }
    float aa = state_a[i];
    float bb = state_b[i];
    float pp = state_p[i];
    float tf = time_first[i];
    float td = time_decay[i];

    float r = 1.0f / (1.0f + expf(-rr));

    float ww = tf + kk;
    float p  = fmaxf(pp, ww);
    float e1 = expf(pp - p);
    float e2 = expf(ww - p);
    float a  = e1 * aa + e2 * vv;
    float b  = e1 * bb + e2;

    float ww2 = pp + td;
    float p2  = fmaxf(ww2, kk);
    float f1  = expf(ww2 - p2);
    float f2  = expf(kk - p2);

    d_out[i]         = 0.0f;               // out accumulator
    d_out[2 * C + i] = f1 * aa + f2 * vv;  // new_state_a
    d_out[3 * C + i] = f1 * bb + f2;       // new_state_b
    d_out[4 * C + i] = p2;                 // new_state_p

    g_rwkv[i] = r * (a / b);
}

// ---------------------------------------------------------------------------
// K_C: out += ow @ (r*wkv), grid (512, 8) = 4096 blocks, 512-col chunks.
// ---------------------------------------------------------------------------
__global__ __launch_bounds__(MV_THREADS)
void matvec_ow_kernel(const float* __restrict__ ow,
                      float* __restrict__ out /* d_out */) {
    int tid  = threadIdx.x;
    int kc   = blockIdx.y;
    int warp = tid >> 5;
    int lane = tid & 31;
    int row  = blockIdx.x * 8 + warp;
    int col0 = kc * 512;

    const float4* Wr = reinterpret_cast<const float4*>(ow + (size_t)row * C + col0);
    const float4* xv = reinterpret_cast<const float4*>(g_rwkv + col0);

    float4 a0 = make_float4(0.f, 0.f, 0.f, 0.f);
    float4 a1 = make_float4(0.f, 0.f, 0.f, 0.f);
    {
        float4 w0 = __ldcs(&Wr[lane +  0]);
        float4 w1 = __ldcs(&Wr[lane + 32]);
        float4 w2 = __ldcs(&Wr[lane + 64]);
        float4 w3 = __ldcs(&Wr[lane + 96]);
        float4 x0 = __ldg(&xv[lane +  0]);
        float4 x1 = __ldg(&xv[lane + 32]);
        float4 x2 = __ldg(&xv[lane + 64]);
        float4 x3 = __ldg(&xv[lane + 96]);
        a0.x = fmaf(w0.x, x0.x, a0.x); a0.y = fmaf(w0.y, x0.y, a0.y);
        a0.z = fmaf(w0.z, x0.z, a0.z); a0.w = fmaf(w0.w, x0.w, a0.w);
        a1.x = fmaf(w1.x, x1.x, a1.x); a1.y = fmaf(w1.y, x1.y, a1.y);
        a1.z = fmaf(w1.z, x1.z, a1.z); a1.w = fmaf(w1.w, x1.w, a1.w);
        a0.x = fmaf(w2.x, x2.x, a0.x); a0.y = fmaf(w2.y, x2.y, a0.y);
        a0.z = fmaf(w2.z, x2.z, a0.z); a0.w = fmaf(w2.w, x2.w, a0.w);
        a1.x = fmaf(w3.x, x3.x, a1.x); a1.y = fmaf(w3.y, x3.y, a1.y);
        a1.z = fmaf(w3.z, x3.z, a1.z); a1.w = fmaf(w3.w, x3.w, a1.w);
    }
    float s = ((a0.x + a0.y) + (a0.z + a0.w))
            + ((a1.x + a1.y) + (a1.z + a1.w));
#pragma unroll
    for (int o = 16; o > 0; o >>= 1)
        s += __shfl_xor_sync(0xFFFFFFFFu, s, o);
    if (lane == 0) atomicAdd(&out[row], s);
}

// ---------------------------------------------------------------------------
// Launch. Input order (metadata): x, state, state_a, state_b, state_p,
// time_mix_k, time_mix_v, time_mix_r, time_first, time_decay, kw, vw, rw, ow.
// Output layout: [out | new_state | new_state_a | new_state_b | new_state_p]
// ---------------------------------------------------------------------------
extern "C" void kernel_launch(void* const* d_in, const int* in_sizes, int n_in,
                              void* d_out, int out_size) {
    const float* x   = (const float*)d_in[0];
    const float* st  = (const float*)d_in[1];
    const float* sa  = (const float*)d_in[2];
    const float* sb  = (const float*)d_in[3];
    const float* sp  = (const float*)d_in[4];
    const float* tmk = (const float*)d_in[5];
    const float* tmv = (const float*)d_in[6];
    const float* tmr = (const float*)d_in[7];
    const float* tf  = (const float*)d_in[8];
    const float* td  = (const float*)d_in[9];
    const float* kw  = (const float*)d_in[10];
    const float* vw  = (const float*)d_in[11];
    const float* rw  = (const float*)d_in[12];
    const float* ow  = (const float*)d_in[13];
    float* out = (float*)d_out;

    dim3 gA(C / 8, KSPLIT_A, 3);          // (512, 4, 3)
    matvec3_fused_kernel<<<gA, MV_THREADS>>>(kw, vw, rw, x, st,
                                             tmk, tmv, tmr, out);

    wkv_kernel<<<C / 256, 256>>>(sa, sb, sp, tf, td, out);

    dim3 gC(C / 8, KSPLIT_OW);            // (512, 8)
    matvec_ow_kernel<<<gC, MV_THREADS>>>(ow, out);
}